// round 1
// baseline (speedup 1.0000x reference)
#include <cuda_runtime.h>
#include <math.h>

#define BSZ  16
#define CDIM 384
#define LDIM 4096
#define PDIM 192
#define BLTOK (BSZ*LDIM)      // 65536
#define NCH  64
#define TCH  64

// ---------------- static scratch (no allocations allowed) ----------------
__device__ float g_fx[(size_t)BLTOK*CDIM];
__device__ float g_bu[(size_t)BLTOK*CDIM];   // packed: cols [0,192)=re, [192,384)=im ; becomes xs after scan
__device__ float g_y [(size_t)BLTOK*CDIM];
__device__ float g_fy[(size_t)BLTOK*CDIM];
__device__ float g_z [(size_t)BLTOK*2*CDIM];
__device__ float g_gg[(size_t)BLTOK*CDIM];
__device__ float g_wb[CDIM*CDIM];            // packed B_bar  [2P, C]
__device__ float g_wc[CDIM*CDIM];            // packed C_eff  [C, 2P]
__device__ float g_lam [2*PDIM];             // lam_bar (re,im)
__device__ float g_lamT[2*PDIM];             // lam_bar^TCH
__device__ float g_carry[(size_t)BSZ*NCH*CDIM];

__device__ __forceinline__ float gelu_f(float v){
    return 0.5f*v*(1.0f + erff(v*0.70710678118654752f));
}

// ---------------- prep: discretization ----------------
__global__ void prep_lam(const float* __restrict__ Lam, const float* __restrict__ logstep){
    int p = threadIdx.x;
    float step = expf(logstep[p]);
    float lre = Lam[2*p], lim = Lam[2*p+1];
    double a  = exp((double)lre*(double)step);
    double th = (double)lim*(double)step;
    g_lam[2*p]   = (float)(a*cos(th));
    g_lam[2*p+1] = (float)(a*sin(th));
    double aT  = exp((double)TCH*(double)lre*(double)step);
    double thT = (double)TCH*th;
    g_lamT[2*p]   = (float)(aT*cos(thT));
    g_lamT[2*p+1] = (float)(aT*sin(thT));
}

// B_bar = ((lam_bar-1)/lam) * Bc ; rows [0,P)=re, [P,2P)=im
__global__ void prep_wb(const float* __restrict__ Lam, const float* __restrict__ Bmat){
    int p = blockIdx.x, c = threadIdx.x;
    float lre = Lam[2*p], lim = Lam[2*p+1];
    float lbr = g_lam[2*p], lbi = g_lam[2*p+1];
    float den = lre*lre + lim*lim;
    float cr = ((lbr-1.0f)*lre + lbi*lim)/den;
    float ci = (lbi*lre - (lbr-1.0f)*lim)/den;
    float br = Bmat[(p*CDIM + c)*2], bi = Bmat[(p*CDIM + c)*2 + 1];
    g_wb[(size_t)p*CDIM + c]        = cr*br - ci*bi;
    g_wb[(size_t)(PDIM+p)*CDIM + c] = cr*bi + ci*br;
}

// C_eff[h, p] = 2*mask*C_re ; C_eff[h, P+p] = -2*mask*C_im  (so y_pre = xs_packed @ C_eff^T = 2*Re(C xs))
__global__ void prep_wc(const float* __restrict__ Lam, const float* __restrict__ logstep,
                        const float* __restrict__ Cmat){
    int h = blockIdx.x, p = threadIdx.x;
    float step = expf(logstep[p]);
    float lim = Lam[2*p+1];
    float freq = step*fabsf(lim)*(float)(1.0/(2.0*3.14159265358979323846));
    float m = (freq < 0.25f) ? 2.0f : 0.0f;
    float cre = Cmat[(h*PDIM + p)*2], cim = Cmat[(h*PDIM + p)*2 + 1];
    g_wc[(size_t)h*CDIM + p]        =  m*cre;
    g_wc[(size_t)h*CDIM + PDIM + p] = -m*cim;
}

// ---------------- LayerNorm 1 : x[B,C,L] (transposed read) -> fx[BL,C] ----------------
__global__ __launch_bounds__(256) void ln1_kernel(const float* __restrict__ x,
                                                  const float* __restrict__ gam,
                                                  const float* __restrict__ bet,
                                                  float* __restrict__ fx){
    __shared__ float tile[CDIM][17];
    int b = blockIdx.y, l0 = blockIdx.x*16;
    int tid = threadIdx.x;
    for (int idx = tid; idx < CDIM*16; idx += 256){
        int c = idx >> 4, j = idx & 15;
        tile[c][j] = x[((size_t)b*CDIM + c)*LDIM + l0 + j];
    }
    __syncthreads();
    int w = tid >> 5, lane = tid & 31;
    for (int j = w*2; j < w*2 + 2; j++){
        float v[12]; float s = 0.0f;
        #pragma unroll
        for (int k = 0; k < 12; k++){ v[k] = tile[lane + 32*k][j]; s += v[k]; }
        #pragma unroll
        for (int o = 16; o; o >>= 1) s += __shfl_xor_sync(0xffffffffu, s, o);
        float mu = s * (1.0f/CDIM);
        float q = 0.0f;
        #pragma unroll
        for (int k = 0; k < 12; k++){ float d = v[k]-mu; q += d*d; }
        #pragma unroll
        for (int o = 16; o; o >>= 1) q += __shfl_xor_sync(0xffffffffu, q, o);
        float inv = rsqrtf(q*(1.0f/CDIM) + 1e-5f);
        size_t row = ((size_t)b*LDIM + l0 + j)*CDIM;
        #pragma unroll
        for (int k = 0; k < 12; k++){
            int c = lane + 32*k;
            fx[row + c] = (v[k]-mu)*inv*gam[c] + bet[c];
        }
    }
}

// ---------------- LayerNorm 2 : y[BL,C] -> fy[BL,C] ----------------
__global__ __launch_bounds__(256) void ln2_kernel(const float* __restrict__ y,
                                                  const float* __restrict__ gam,
                                                  const float* __restrict__ bet,
                                                  float* __restrict__ fy){
    int row  = blockIdx.x*8 + (threadIdx.x >> 5);
    int lane = threadIdx.x & 31;
    const float4* r4 = (const float4*)(y + (size_t)row*CDIM);
    float4 v[3]; float s = 0.0f;
    #pragma unroll
    for (int k = 0; k < 3; k++){ v[k] = r4[lane + 32*k]; s += v[k].x+v[k].y+v[k].z+v[k].w; }
    #pragma unroll
    for (int o = 16; o; o >>= 1) s += __shfl_xor_sync(0xffffffffu, s, o);
    float mu = s * (1.0f/CDIM);
    float q = 0.0f;
    #pragma unroll
    for (int k = 0; k < 3; k++){
        float dx=v[k].x-mu, dy=v[k].y-mu, dz=v[k].z-mu, dw=v[k].w-mu;
        q += dx*dx+dy*dy+dz*dz+dw*dw;
    }
    #pragma unroll
    for (int o = 16; o; o >>= 1) q += __shfl_xor_sync(0xffffffffu, q, o);
    float inv = rsqrtf(q*(1.0f/CDIM) + 1e-5f);
    float4* o4 = (float4*)(fy + (size_t)row*CDIM);
    const float4* g4 = (const float4*)gam;
    const float4* b4 = (const float4*)bet;
    #pragma unroll
    for (int k = 0; k < 3; k++){
        int c4 = lane + 32*k;
        float4 gg = g4[c4], bb = b4[c4], r;
        r.x = (v[k].x-mu)*inv*gg.x + bb.x;
        r.y = (v[k].y-mu)*inv*gg.y + bb.y;
        r.z = (v[k].z-mu)*inv*gg.z + bb.z;
        r.w = (v[k].w-mu)*inv*gg.w + bb.w;
        o4[c4] = r;
    }
}

// ---------------- SGEMM NT: C[M,N] = A[M,K] @ B[N,K]^T, fused epilogues ----------------
// EPI 0: plain   EPI 1: v=acc+D[n]*fx; out=gelu(v)+fx   EPI 2: out=acc+e0
template<int EPI>
__global__ __launch_bounds__(256,2) void sgemm_nt(const float* __restrict__ A,
                                                  const float* __restrict__ Bm,
                                                  float* __restrict__ Cout,
                                                  int N, int K,
                                                  const float* __restrict__ e0,
                                                  const float* __restrict__ e1){
    __shared__ float As[16][128];
    __shared__ float Bs[16][128];
    int bm = blockIdx.y*128, bn = blockIdx.x*128;
    int tid = threadIdx.x;
    int tr = tid >> 4, tc = tid & 15;
    float acc[8][8] = {};
    const float* Ab = A  + (size_t)bm*K;
    const float* Bb = Bm + (size_t)bn*K;
    for (int k0 = 0; k0 < K; k0 += 16){
        #pragma unroll
        for (int i = 0; i < 2; i++){
            int lin = tid + i*256;
            int row = lin >> 2;
            int kc  = (lin & 3) << 2;
            float4 va = *(const float4*)(Ab + (size_t)row*K + k0 + kc);
            As[kc][row]=va.x; As[kc+1][row]=va.y; As[kc+2][row]=va.z; As[kc+3][row]=va.w;
            float4 vb = *(const float4*)(Bb + (size_t)row*K + k0 + kc);
            Bs[kc][row]=vb.x; Bs[kc+1][row]=vb.y; Bs[kc+2][row]=vb.z; Bs[kc+3][row]=vb.w;
        }
        __syncthreads();
        #pragma unroll
        for (int k = 0; k < 16; k++){
            float a[8], b[8];
            *(float4*)&a[0] = *(const float4*)&As[k][tr*8];
            *(float4*)&a[4] = *(const float4*)&As[k][tr*8+4];
            *(float4*)&b[0] = *(const float4*)&Bs[k][tc*8];
            *(float4*)&b[4] = *(const float4*)&Bs[k][tc*8+4];
            #pragma unroll
            for (int i = 0; i < 8; i++)
                #pragma unroll
                for (int j = 0; j < 8; j++)
                    acc[i][j] = fmaf(a[i], b[j], acc[i][j]);
        }
        __syncthreads();
    }
    #pragma unroll
    for (int i = 0; i < 8; i++){
        size_t m = (size_t)bm + tr*8 + i;
        float* outp = Cout + m*(size_t)N + bn + tc*8;
        float o[8];
        if (EPI == 0){
            #pragma unroll
            for (int j = 0; j < 8; j++) o[j] = acc[i][j];
        } else {
            const float* ep = e0 + m*(size_t)CDIM + bn + tc*8;
            float f[8];
            *(float4*)&f[0] = *(const float4*)ep;
            *(float4*)&f[4] = *(const float4*)(ep+4);
            if (EPI == 1){
                #pragma unroll
                for (int j = 0; j < 8; j++){
                    float v = acc[i][j] + e1[bn + tc*8 + j]*f[j];
                    o[j] = gelu_f(v) + f[j];
                }
            } else {
                #pragma unroll
                for (int j = 0; j < 8; j++) o[j] = acc[i][j] + f[j];
            }
        }
        *(float4*)&outp[0] = *(float4*)&o[0];
        *(float4*)&outp[4] = *(float4*)&o[4];
    }
}

// ---------------- chunked constant-coefficient complex scan ----------------
__global__ void scan_a(float* __restrict__ bu, float* __restrict__ carry){
    int p = threadIdx.x, ch = blockIdx.x, b = blockIdx.y;
    float lre = g_lam[2*p], lim = g_lam[2*p+1];
    float sre = 0.0f, sim = 0.0f;
    size_t base = ((size_t)b*LDIM + (size_t)ch*TCH)*CDIM;
    for (int i = 0; i < TCH; i++){
        size_t idx = base + (size_t)i*CDIM;
        float br = bu[idx+p], bi = bu[idx+PDIM+p];
        float nr = fmaf(lre, sre, fmaf(-lim, sim, br));
        float ni = fmaf(lre, sim, fmaf( lim, sre, bi));
        bu[idx+p] = nr; bu[idx+PDIM+p] = ni;
        sre = nr; sim = ni;
    }
    size_t cidx = ((size_t)b*NCH + ch)*CDIM;
    carry[cidx+p] = sre; carry[cidx+PDIM+p] = sim;
}

__global__ void scan_b(float* __restrict__ carry){
    int p = threadIdx.x, b = blockIdx.x;
    float tr = g_lamT[2*p], ti = g_lamT[2*p+1];
    float pr = 0.0f, pi = 0.0f;
    for (int k = 0; k < NCH; k++){
        size_t ci = ((size_t)b*NCH + k)*CDIM;
        float cr = carry[ci+p], cm = carry[ci+PDIM+p];
        carry[ci+p] = pr; carry[ci+PDIM+p] = pi;      // exclusive prefix
        float nr = fmaf(tr, pr, fmaf(-ti, pi, cr));
        float ni = fmaf(tr, pi, fmaf( ti, pr, cm));
        pr = nr; pi = ni;
    }
}

__global__ void scan_c(float* __restrict__ bu, const float* __restrict__ carry){
    int p = threadIdx.x, ch = blockIdx.x, b = blockIdx.y;
    if (ch == 0) return;
    size_t cidx = ((size_t)b*NCH + ch)*CDIM;
    float sre = carry[cidx+p], sim = carry[cidx+PDIM+p];
    float lre = g_lam[2*p], lim = g_lam[2*p+1];
    float pr = lre, pi = lim;                // lam^1
    size_t base = ((size_t)b*LDIM + (size_t)ch*TCH)*CDIM;
    for (int i = 0; i < TCH; i++){
        size_t idx = base + (size_t)i*CDIM;
        bu[idx+p]      += pr*sre - pi*sim;
        bu[idx+PDIM+p] += pr*sim + pi*sre;
        float nr = pr*lre - pi*lim;
        pi = pr*lim + pi*lre;
        pr = nr;
    }
}

// ---------------- GEGLU ----------------
__global__ void geglu_kernel(const float4* __restrict__ z, float4* __restrict__ g){
    int i = blockIdx.x*blockDim.x + threadIdx.x;   // i < BLTOK*96 exactly
    int m = i / 96, h = i - m*96;
    float4 a = z[(size_t)m*192 + h];
    float4 q = z[(size_t)m*192 + 96 + h];
    float4 o;
    o.x = a.x*gelu_f(q.x); o.y = a.y*gelu_f(q.y);
    o.z = a.z*gelu_f(q.z); o.w = a.w*gelu_f(q.w);
    g[i] = o;
}

// ---------------- final transpose [BL,C] -> [B,C,L] ----------------
__global__ void transpose_out(const float* __restrict__ y2, float* __restrict__ out){
    __shared__ float t[32][33];
    int b = blockIdx.z, c0 = blockIdx.y*32, l0 = blockIdx.x*32;
    int tx = threadIdx.x, ty = threadIdx.y;
    for (int i = ty; i < 32; i += 8)
        t[i][tx] = y2[((size_t)b*LDIM + l0 + i)*CDIM + c0 + tx];
    __syncthreads();
    for (int i = ty; i < 32; i += 8)
        out[((size_t)b*CDIM + c0 + i)*LDIM + l0 + tx] = t[tx][i];
}

// ---------------- launch ----------------
extern "C" void kernel_launch(void* const* d_in, const int* in_sizes, int n_in,
                              void* d_out, int out_size){
    const float* x       = (const float*)d_in[0];
    const float* ln1g    = (const float*)d_in[1];
    const float* ln1b    = (const float*)d_in[2];
    const float* Lam     = (const float*)d_in[3];
    const float* Bmat    = (const float*)d_in[4];
    const float* Cmat    = (const float*)d_in[5];
    const float* Dv      = (const float*)d_in[6];
    const float* logstep = (const float*)d_in[7];
    const float* ln2g    = (const float*)d_in[8];
    const float* ln2b    = (const float*)d_in[9];
    const float* Wenc    = (const float*)d_in[10];
    const float* Wdec    = (const float*)d_in[11];
    float* out = (float*)d_out;

    float *fx,*bu,*y,*fy,*z,*gg,*wb,*wc,*carry;
    cudaGetSymbolAddress((void**)&fx,    g_fx);
    cudaGetSymbolAddress((void**)&bu,    g_bu);
    cudaGetSymbolAddress((void**)&y,     g_y);
    cudaGetSymbolAddress((void**)&fy,    g_fy);
    cudaGetSymbolAddress((void**)&z,     g_z);
    cudaGetSymbolAddress((void**)&gg,    g_gg);
    cudaGetSymbolAddress((void**)&wb,    g_wb);
    cudaGetSymbolAddress((void**)&wc,    g_wc);
    cudaGetSymbolAddress((void**)&carry, g_carry);

    prep_lam<<<1, PDIM>>>(Lam, logstep);
    prep_wb<<<PDIM, CDIM>>>(Lam, Bmat);
    prep_wc<<<CDIM, PDIM>>>(Lam, logstep, Cmat);

    ln1_kernel<<<dim3(LDIM/16, BSZ), 256>>>(x, ln1g, ln1b, fx);

    // Bu = fx @ Bbar_packed^T   -> [BL, 2P]
    sgemm_nt<0><<<dim3(3, 512), 256>>>(fx, wb, bu, CDIM, CDIM, nullptr, nullptr);

    scan_a<<<dim3(NCH, BSZ), PDIM>>>(bu, carry);
    scan_b<<<BSZ, PDIM>>>(carry);
    scan_c<<<dim3(NCH, BSZ), PDIM>>>(bu, carry);

    // y = gelu(xs @ Ceff^T + D*fx) + fx
    sgemm_nt<1><<<dim3(3, 512), 256>>>(bu, wc, y, CDIM, CDIM, fx, Dv);

    ln2_kernel<<<BLTOK/8, 256>>>(y, ln2g, ln2b, fy);

    // z = fy @ Wenc^T  -> [BL, 768]
    sgemm_nt<0><<<dim3(6, 512), 256>>>(fy, Wenc, z, 2*CDIM, CDIM, nullptr, nullptr);

    geglu_kernel<<<(BLTOK*96)/256, 256>>>((const float4*)z, (float4*)gg);

    // y2 = gg @ Wdec^T + fy   (reuse g_y)
    sgemm_nt<2><<<dim3(3, 512), 256>>>(gg, Wdec, y, CDIM, CDIM, fy, nullptr);

    transpose_out<<<dim3(LDIM/32, CDIM/32, BSZ), dim3(32, 8)>>>(y, out);
}